// round 5
// baseline (speedup 1.0000x reference)
#include <cuda_runtime.h>
#include <cstdint>

#define BATCH 512
#define TLEN  1024
#define NST   64

typedef unsigned long long ull;

// Packed f32x2 helpers (Blackwell FFMA2 path — only reachable via PTX f32x2)
#define FMA2(d, a, b, c) asm("fma.rn.f32x2 %0, %1, %2, %3;" : "=l"(d) : "l"(a), "l"(b), "l"(c))
#define ADD2(d, a, b)    asm("add.rn.f32x2 %0, %1, %2;"     : "=l"(d) : "l"(a), "l"(b))
#define UNPACK2(lo, hi, s) asm("mov.b64 {%0, %1}, %2;"      : "=f"(lo), "=f"(hi) : "l"(s))

__device__ __forceinline__ float fexp(float x) {
    float y;
    asm("ex2.approx.f32 %0, %1;" : "=f"(y) : "f"(x * 1.4426950408889634f));
    return y;
}
__device__ __forceinline__ float ex2f(float x) {
    float y;
    asm("ex2.approx.f32 %0, %1;" : "=f"(y) : "f"(x));
    return y;
}
__device__ __forceinline__ float flog(float x) {
    float y;
    asm("lg2.approx.f32 %0, %1;" : "=f"(y) : "f"(x));
    return y * 0.6931471805599453f;
}

// Transposed i-pair packing:
// g_Ep[c][k] = ( exp(trans[2k][c]), exp(trans[2k+1][c]) ),  c in [0,64), k in [0,32)
__device__ __align__(16) float2 g_Ep[NST][NST / 2];

__global__ void prep_kernel(const float* __restrict__ trans) {
    for (int idx = threadIdx.x; idx < NST * (NST / 2); idx += blockDim.x) {
        int c = idx >> 5, k = idx & 31;
        g_Ep[c][k] = make_float2(expf(trans[(2 * k) * NST + c]),
                                 expf(trans[(2 * k + 1) * NST + c]));
    }
}

// One CTA (64 threads = 2 warps) per chain; thread tid owns column c = tid.
// Per step: 32 FFMA2 (i packed in f32x2 pairs), pair lanes folded locally.
// Exchange: STS.32 publish + __syncthreads + 16 broadcast LDS.128.
// Loop body is fully branch-free: renorm every step via lag-2 exponent ring.
__global__ void __launch_bounds__(64) crf_kernel(
    const float* __restrict__ unary,
    const int*   __restrict__ lengths,
    float*       __restrict__ out)
{
    const int tid = threadIdx.x;
    const int W   = tid >> 5;
    const int l   = tid & 31;
    const int b   = blockIdx.x;
    const int c   = tid;

    // E column slice in registers: 32 packed i-pairs (64 regs)
    ull cE[32];
    const ull* Ep = (const ull*)g_Ep;
    #pragma unroll
    for (int k = 0; k < 32; k++)
        cE[k] = Ep[c * 32 + k];

    __shared__ __align__(16) float wbuf[2][NST];
    __shared__ int   sexp[4];   // depth-4 exponent ring, lag 2
    __shared__ float ssum[2];

    int len = lengths[b];
    if (len < 1) len = 1;
    const float* ub = unary + (size_t)b * (TLEN * NST);
    const float* pc = ub + c;

    // w0 = exp(u0) for my column
    float w = fexp(pc[0]);
    wbuf[0][c] = w;
    if (tid == 0) { sexp[0] = 0; sexp[1] = 0; sexp[2] = 0; sexp[3] = 0; }

    int ktot = 0;
    // distance-3 register prefetch pipeline of this thread's unary column
    float uA = 0.f, uB = 0.f, uC = 0.f;
    if (len > 1) uA = pc[NST];
    uB = (len > 2) ? pc[2 * NST] : uA;
    uC = (len > 3) ? pc[3 * NST] : uB;
    // pointer to u_{min(4, len-1)} for the rolling load
    const float* up = pc + (size_t)((len - 1 < 4) ? (len - 1) : 4) * NST;

    const float L2E = 1.4426950408889634f;
    int buf = 0;

    for (int t = 1; t < len; t++) {
        __syncthreads();

        // lag-2 renorm apply (published at end of step t-2; 2 barriers ago)
        int e = sexp[(t + 2) & 3];   // (t-2)&3 == (t+2)&3
        ktot += e;
        // eu = exp(u_t) * 2^-e, one MUFU, hoisted before the FFMA stream
        float eu = ex2f(fmaf(uA, L2E, -(float)e));

        // matvec for my column: 16 broadcast LDS.128 + 32 FFMA2
        const ulonglong2* P = (const ulonglong2*)wbuf[buf];
        ull a0 = 0ull, a1 = 0ull, a2 = 0ull, a3 = 0ull;
        #pragma unroll
        for (int m = 0; m < 16; m += 2) {
            ulonglong2 x = P[m];
            ulonglong2 y = P[m + 1];
            FMA2(a0, x.x, cE[2 * m + 0], a0);
            FMA2(a1, x.y, cE[2 * m + 1], a1);
            FMA2(a2, y.x, cE[2 * m + 2], a2);
            FMA2(a3, y.y, cE[2 * m + 3], a3);
        }
        ADD2(a0, a0, a1);
        ADD2(a2, a2, a3);
        ADD2(a0, a0, a2);
        float slo, shi;
        UNPACK2(slo, shi, a0);
        w = (slo + shi) * eu;

        // shift unary pipeline (distance 3); selp-guarded pointer walk
        uA = uB; uB = uC;
        uC = *up;
        up += (t + 4 < len) ? NST : 0;

        // publish my-exponent (thread 0 only; single predicated STS, no branch)
        int myE = ((__float_as_int(w) >> 23) & 255) - 127;
        myE = min(max(myE, -100), 100);
        if (tid == 0) sexp[t & 3] = myE;

        wbuf[buf ^ 1][c] = w;
        buf ^= 1;
    }

    // out[b] = ktot*ln2 + log(sum_j w_j)  (warp reduce + cross-warp via smem)
    float s = w;
    #pragma unroll
    for (int off = 16; off; off >>= 1)
        s += __shfl_xor_sync(0xffffffffu, s, off);
    if (l == 0) ssum[W] = s;
    __syncthreads();
    if (tid == 0)
        out[b] = (float)ktot * 0.6931471805599453f + flog(ssum[0] + ssum[1]);
}

extern "C" void kernel_launch(void* const* d_in, const int* in_sizes, int n_in,
                              void* d_out, int out_size) {
    const float* unary   = nullptr;
    const int*   lengths = nullptr;
    const float* trans   = nullptr;
    for (int i = 0; i < n_in; i++) {
        if (in_sizes[i] == BATCH * TLEN * NST) unary   = (const float*)d_in[i];
        else if (in_sizes[i] == BATCH)         lengths = (const int*)d_in[i];
        else if (in_sizes[i] == NST * NST)     trans   = (const float*)d_in[i];
    }
    prep_kernel<<<1, 256>>>(trans);
    crf_kernel<<<BATCH, 64>>>(unary, lengths, (float*)d_out);
}

// round 6
// speedup vs baseline: 1.1366x; 1.1366x over previous
#include <cuda_runtime.h>
#include <cstdint>

#define BATCH 512
#define TLEN  1024
#define NST   64

typedef unsigned long long ull;

// Packed f32x2 helpers (Blackwell FFMA2 path — only reachable via PTX f32x2)
#define FMA2(d, a, b, c) asm("fma.rn.f32x2 %0, %1, %2, %3;" : "=l"(d) : "l"(a), "l"(b), "l"(c))
#define ADD2(d, a, b)    asm("add.rn.f32x2 %0, %1, %2;"     : "=l"(d) : "l"(a), "l"(b))
#define UNPACK2(lo, hi, s) asm("mov.b64 {%0, %1}, %2;"      : "=f"(lo), "=f"(hi) : "l"(s))

#define CHAIN_BAR(q) asm volatile("bar.sync %0, 64;" :: "r"(1 + (q)) : "memory")

__device__ __forceinline__ float fexp(float x) {
    float y;
    asm("ex2.approx.f32 %0, %1;" : "=f"(y) : "f"(x * 1.4426950408889634f));
    return y;
}
__device__ __forceinline__ float ex2f(float x) {
    float y;
    asm("ex2.approx.f32 %0, %1;" : "=f"(y) : "f"(x));
    return y;
}
__device__ __forceinline__ float flog(float x) {
    float y;
    asm("lg2.approx.f32 %0, %1;" : "=f"(y) : "f"(x));
    return y * 0.6931471805599453f;
}

// Transposed i-pair packing:
// g_Ep[c][k] = ( exp(trans[2k][c]), exp(trans[2k+1][c]) ),  c in [0,64), k in [0,32)
__device__ __align__(16) float2 g_Ep[NST][NST / 2];

__global__ void prep_kernel(const float* __restrict__ trans) {
    for (int idx = threadIdx.x; idx < NST * (NST / 2); idx += blockDim.x) {
        int c = idx >> 5, k = idx & 31;
        g_Ep[c][k] = make_float2(expf(trans[(2 * k) * NST + c]),
                                 expf(trans[(2 * k + 1) * NST + c]));
    }
}

// 2 chains per 128-thread CTA. Chain q uses warps {2q, 2q+1} -> SMSPs {0,1} / {2,3},
// so all 4 SMSPs carry load (block=64 left SMSP 2,3 idle chip-wide).
// Thread owns column c = (wid&1)*32 + lane; full 64-MAC i-sum as 32 FFMA2.
// Per-chain named barrier (bar.sync 1+q, 64) keeps early-exit decoupled.
__global__ void __launch_bounds__(128) crf_kernel(
    const float* __restrict__ unary,
    const int*   __restrict__ lengths,
    float*       __restrict__ out)
{
    const int tid  = threadIdx.x;
    const int wid  = tid >> 5;
    const int lane = tid & 31;
    const int q    = wid >> 1;                 // chain slot in CTA (0 or 1)
    const int c    = ((wid & 1) << 5) | lane;  // my column within the chain
    const int b    = (blockIdx.x << 1) + q;

    // E column slice in registers: 32 packed i-pairs (64 regs)
    ull cE[32];
    const ull* Ep = (const ull*)g_Ep;
    #pragma unroll
    for (int k = 0; k < 32; k++)
        cE[k] = Ep[c * 32 + k];

    __shared__ __align__(16) float wbuf[2][2][NST];  // [chain][buf][col]
    __shared__ int   sexp[2];                         // [chain] lag-2 exponent
    __shared__ float ssum[2][2];                      // [chain][warp-half]

    int len = lengths[b];
    if (len < 1) len = 1;
    const float* ub = unary + (size_t)b * (TLEN * NST);
    const float* pc = ub + c;

    // w0 = exp(u0) for my column
    float w = fexp(pc[0]);
    wbuf[q][0][c] = w;

    int ktot = 0;
    // distance-3 register prefetch pipeline of this thread's unary column
    float uA = 0.f, uB = 0.f, uC = 0.f;
    if (len > 1) uA = pc[NST];
    uB = (len > 2) ? pc[2 * NST] : uA;
    uC = (len > 3) ? pc[3 * NST] : uB;
    const float* up = pc + (size_t)((len - 1 < 4) ? (len - 1) : 4) * NST;

    const float L2E = 1.4426950408889634f;
    int buf = 0;

    for (int t = 1; t < len; t++) {
        CHAIN_BAR(q);

        // lagged renorm apply (published 2 steps ago), folded into the MUFU arg
        float kf = 0.0f;
        if ((t & 3) == 2 && t >= 6) {
            int e = sexp[q];
            ktot += e;
            kf = (float)e;
        }
        // hoisted before the FFMA stream so MUFU latency hides under it
        float eu = ex2f(fmaf(uA, L2E, -kf));

        // matvec for my column: 16 broadcast LDS.128 + 32 FFMA2
        const ulonglong2* P = (const ulonglong2*)wbuf[q][buf];
        ull a0 = 0ull, a1 = 0ull, a2 = 0ull, a3 = 0ull;
        #pragma unroll
        for (int m = 0; m < 16; m += 2) {
            ulonglong2 x = P[m];
            ulonglong2 y = P[m + 1];
            FMA2(a0, x.x, cE[2 * m + 0], a0);
            FMA2(a1, x.y, cE[2 * m + 1], a1);
            FMA2(a2, y.x, cE[2 * m + 2], a2);
            FMA2(a3, y.y, cE[2 * m + 3], a3);
        }
        ADD2(a0, a0, a1);
        ADD2(a2, a2, a3);
        ADD2(a0, a0, a2);
        float slo, shi;
        UNPACK2(slo, shi, a0);
        w = (slo + shi) * eu;

        // shift unary pipeline (distance 3); selp-guarded pointer walk
        uA = uB; uB = uC;
        uC = *up;
        up += (t + 4 < len) ? NST : 0;

        // renorm publish: column-0 thread's exponent, applied at t+2
        if ((t & 3) == 0 && c == 0) {
            int e = ((__float_as_int(w) >> 23) & 255) - 127;
            e = min(max(e, -100), 100);
            sexp[q] = e;
        }

        wbuf[q][buf ^ 1][c] = w;
        buf ^= 1;
    }

    // out[b] = ktot*ln2 + log(sum_j w_j): warp reduce, combine 2 warps via smem
    float s = w;
    #pragma unroll
    for (int off = 16; off; off >>= 1)
        s += __shfl_xor_sync(0xffffffffu, s, off);
    if (lane == 0) ssum[q][wid & 1] = s;
    CHAIN_BAR(q);
    if (c == 0)
        out[b] = (float)ktot * 0.6931471805599453f + flog(ssum[q][0] + ssum[q][1]);
}

extern "C" void kernel_launch(void* const* d_in, const int* in_sizes, int n_in,
                              void* d_out, int out_size) {
    const float* unary   = nullptr;
    const int*   lengths = nullptr;
    const float* trans   = nullptr;
    for (int i = 0; i < n_in; i++) {
        if (in_sizes[i] == BATCH * TLEN * NST) unary   = (const float*)d_in[i];
        else if (in_sizes[i] == BATCH)         lengths = (const int*)d_in[i];
        else if (in_sizes[i] == NST * NST)     trans   = (const float*)d_in[i];
    }
    prep_kernel<<<1, 256>>>(trans);
    crf_kernel<<<BATCH / 2, 128>>>(unary, lengths, (float*)d_out);
}